// round 10
// baseline (speedup 1.0000x reference)
#include <cuda_runtime.h>
#include <cstdint>
#include <cstddef>

// ============================================================================
// out[8192,4096] = x[8192,4096] @ ternarize(W)[4096,4096]^T, fp32.
// TF32 mma.sync path (proven-passing R2 structure), plus:
//   - W stored k-octet-interleaved in gmem so B fragments load as one
//     ld.shared.v2.b32 instead of two ld.shared.b32 (halves B LDS issue).
// Ternary weights exact in tf32; x -> cvt.rna.tf32 (rel err ~1e-4 measured).
// ============================================================================
#define M_DIM 8192
#define N_DIM 4096
#define K_DIM 4096

#define BM 128
#define BN 128
#define BK 32
#define STAGES 3
#define K_ITERS (K_DIM / BK)        // 128
#define THREADS 256

#define A_STAGE_BYTES (BM * BK * 4)          // 16384
#define B_STAGE_BYTES (BN * BK * 4)          // 16384
#define STAGE_BYTES   (A_STAGE_BYTES + B_STAGE_BYTES)   // 32768
#define SMEM_TOTAL    (STAGES * STAGE_BYTES)            // 98304

// Ternarized, k-octet-interleaved weight scratch (f32, exact in tf32).
// Per 8 k: stored order [k0,k4,k1,k5,k2,k6,k3,k7]  => logical (q, q+4)
// live at positions (2q, 2q+1): one 8-byte fragment load.
__device__ __align__(16) float g_Wt[(size_t)N_DIM * K_DIM];   // 64 MB

// ============================================================================
// Helpers
// ============================================================================
__device__ __forceinline__ uint32_t smem_u32(const void* p) {
    uint32_t a;
    asm("{ .reg .u64 t; cvta.to.shared.u64 t, %1; cvt.u32.u64 %0, t; }" : "=r"(a) : "l"(p));
    return a;
}
__device__ __forceinline__ void cp_async16(uint32_t dst, const void* src) {
    asm volatile("cp.async.cg.shared.global [%0], [%1], 16;" :: "r"(dst), "l"(src) : "memory");
}
__device__ __forceinline__ void cp_commit() { asm volatile("cp.async.commit_group;" ::: "memory"); }
__device__ __forceinline__ void cp_wait1()  { asm volatile("cp.async.wait_group 1;" ::: "memory"); }

__device__ __forceinline__ float lds_f32(uint32_t addr) {
    float v;
    asm volatile("ld.shared.f32 %0, [%1];" : "=f"(v) : "r"(addr));
    return v;
}
__device__ __forceinline__ uint2 lds_u64(uint32_t addr) {
    uint2 v;
    asm volatile("ld.shared.v2.b32 {%0, %1}, [%2];" : "=r"(v.x), "=r"(v.y) : "r"(addr));
    return v;
}
__device__ __forceinline__ uint32_t f2tf32(float v) {
    uint32_t o;
    asm("cvt.rna.tf32.f32 %0, %1;" : "=r"(o) : "f"(v));
    return o;
}
__device__ __forceinline__ void mma_tf32(float& d0, float& d1, float& d2, float& d3,
                                         uint32_t a0, uint32_t a1, uint32_t a2, uint32_t a3,
                                         uint32_t b0, uint32_t b1) {
    asm volatile("mma.sync.aligned.m16n8k8.row.col.f32.tf32.tf32.f32 "
                 "{%0,%1,%2,%3}, {%4,%5,%6,%7}, {%8,%9}, {%0,%1,%2,%3};"
                 : "+f"(d0), "+f"(d1), "+f"(d2), "+f"(d3)
                 : "r"(a0), "r"(a1), "r"(a2), "r"(a3), "r"(b0), "r"(b1));
}

// Swizzled smem offset for tile element (row, col): row-major, 32 f32/row,
// 16B chunks XOR-permuted by row to kill bank conflicts.  (A tile, natural k)
__device__ __forceinline__ uint32_t tile_off(int row, int col) {
    return (uint32_t)(row * 128 + ((((col >> 2) ^ (row & 7)) << 4) | ((col & 3) << 2)));
}

// ============================================================================
// W ternarize + k-octet interleave: per octet o (8 consecutive k),
// write [t(k0),t(k4),t(k1),t(k5)] , [t(k2),t(k6),t(k3),t(k7)]
// ============================================================================
__device__ __forceinline__ float tern(float w) {
    float r = rintf(w);                       // half-to-even, matches jnp.round
    return (r > 0.f) ? 1.f : ((r < 0.f) ? -1.f : 0.f);
}
__global__ void cvt_w_kernel(const float* __restrict__ w) {
    size_t o = (size_t)blockIdx.x * blockDim.x + threadIdx.x;   // octet id, 2097152 total
    const float4* p = reinterpret_cast<const float4*>(w + o * 8);
    float4 lo4 = p[0];          // k0..k3
    float4 hi4 = p[1];          // k4..k7
    float4 o0 = make_float4(tern(lo4.x), tern(hi4.x), tern(lo4.y), tern(hi4.y));
    float4 o1 = make_float4(tern(lo4.z), tern(hi4.z), tern(lo4.w), tern(hi4.w));
    float4* q = reinterpret_cast<float4*>(g_Wt + o * 8);
    q[0] = o0;
    q[1] = o1;
}

// ============================================================================
// GEMM kernel
// ============================================================================
__global__ __launch_bounds__(THREADS, 2) void ternary_gemm_kernel(
    const float* __restrict__ x, float* __restrict__ out) {
    extern __shared__ char smem[];
    const uint32_t sb = smem_u32(smem);
    const int tid = threadIdx.x;

    // --- supergrouped rasterization: 8 M-tiles x all 32 N-tiles per group ---
    const int TILES_N = N_DIM / BN;           // 32
    const int GM = 8;
    const int per_super = GM * TILES_N;       // 256
    int gid = blockIdx.x;
    int sg = gid / per_super;
    int r  = gid % per_super;
    const int M0 = (sg * GM + (r % GM)) * BM;
    const int N0 = (r / GM) * BN;

    // --- loader address precompute: 4 A-chunks + 4 B-chunks per thread ------
    const float* srcA[4];
    const float* srcB[4];
    uint32_t dstOff[4];
#pragma unroll
    for (int t = 0; t < 4; t++) {
        int cid = tid + t * 256;
        int row = cid >> 3;
        int ch  = cid & 7;
        srcA[t] = x    + (size_t)(M0 + row) * K_DIM + ch * 4;
        srcB[t] = g_Wt + (size_t)(N0 + row) * K_DIM + ch * 4;
        dstOff[t] = (uint32_t)(row * 128 + ((ch ^ (row & 7)) << 4));
    }

    auto issue_stage = [&](int i) {
        const int k0 = i * BK;
        const uint32_t aS = sb + (i % STAGES) * STAGE_BYTES;
        const uint32_t bS = aS + A_STAGE_BYTES;
#pragma unroll
        for (int t = 0; t < 4; t++) cp_async16(aS + dstOff[t], srcA[t] + k0);
#pragma unroll
        for (int t = 0; t < 4; t++) cp_async16(bS + dstOff[t], srcB[t] + k0);
        cp_commit();
    };

    // prologue: 2 stages in flight
    issue_stage(0);
    issue_stage(1);

    // --- warp tiling: 4 warps on M (32 rows each), 2 on N (64 cols each) ----
    const int wid = tid >> 5;
    const int lane = tid & 31;
    const int grp = lane >> 2;                // 0..7
    const int qid = lane & 3;                 // 0..3
    const int wmBase = (wid & 3) * 32;
    const int wnBase = (wid >> 2) * 64;
    const uint32_t bQoff = (uint32_t)(((qid & 1) << 3) | ((qid >> 1) << 4)); // chunk-half select

    float acc[2][8][4];
#pragma unroll
    for (int mt = 0; mt < 2; mt++)
#pragma unroll
        for (int nt = 0; nt < 8; nt++)
#pragma unroll
            for (int j = 0; j < 4; j++) acc[mt][nt][j] = 0.f;

#pragma unroll 1
    for (int i = 0; i < K_ITERS; i++) {
        cp_wait1();                // stage i landed
        __syncthreads();           // everyone done reading buf (i-1)%3 too
        if (i + 2 < K_ITERS) issue_stage(i + 2);
        else cp_commit();          // keep group accounting uniform

        const uint32_t aS = sb + (i % STAGES) * STAGE_BYTES;
        const uint32_t bS = aS + A_STAGE_BYTES;

#pragma unroll
        for (int ks = 0; ks < 4; ks++) {
            const int k = ks * 8;
            // A fragments (2 m-tiles x 4 regs), cvt.rna -> tf32 (natural layout)
            uint32_t a[2][4];
#pragma unroll
            for (int mt = 0; mt < 2; mt++) {
                int r0 = wmBase + mt * 16 + grp;
                a[mt][0] = f2tf32(lds_f32(aS + tile_off(r0,     k + qid)));
                a[mt][1] = f2tf32(lds_f32(aS + tile_off(r0 + 8, k + qid)));
                a[mt][2] = f2tf32(lds_f32(aS + tile_off(r0,     k + qid + 4)));
                a[mt][3] = f2tf32(lds_f32(aS + tile_off(r0 + 8, k + qid + 4)));
            }
            // B fragments: interleaved layout => (k+qid, k+qid+4) adjacent.
            // permuted col' = ks*8 + 2*qid ; chunk = 2*ks + (qid>>1);
            // byte-in-chunk = (qid&1)*8. Swizzle: chunk XOR (row&7).
#pragma unroll
            for (int nt = 0; nt < 8; nt++) {
                int n = wnBase + nt * 8 + grp;
                uint32_t boff = (uint32_t)(n * 128 +
                                 ((((2 * ks + (qid >> 1)) ^ (n & 7)) << 4) | ((qid & 1) << 3)));
                uint2 bv = lds_u64(bS + boff);
#pragma unroll
                for (int mt = 0; mt < 2; mt++)
                    mma_tf32(acc[mt][nt][0], acc[mt][nt][1], acc[mt][nt][2], acc[mt][nt][3],
                             a[mt][0], a[mt][1], a[mt][2], a[mt][3],
                             bv.x, bv.y);
            }
        }
    }

    // --- epilogue: direct STG.64 (float2), coalesced per 8-col n-tile -------
#pragma unroll
    for (int mt = 0; mt < 2; mt++) {
        int row0 = M0 + wmBase + mt * 16 + grp;
#pragma unroll
        for (int nt = 0; nt < 8; nt++) {
            int col = N0 + wnBase + nt * 8 + qid * 2;
            float2 v0 = make_float2(acc[mt][nt][0], acc[mt][nt][1]);
            float2 v1 = make_float2(acc[mt][nt][2], acc[mt][nt][3]);
            *reinterpret_cast<float2*>(out + (size_t)row0 * N_DIM + col)       = v0;
            *reinterpret_cast<float2*>(out + (size_t)(row0 + 8) * N_DIM + col) = v1;
        }
    }
}

// ============================================================================
// Launch
// ============================================================================
extern "C" void kernel_launch(void* const* d_in, const int* in_sizes, int n_in,
                              void* d_out, int out_size) {
    const float* x = (const float*)d_in[0];       // [8192, 4096]
    const float* w = (const float*)d_in[1];       // [4096, 4096]
    float* out = (float*)d_out;                   // [8192, 4096]

    cvt_w_kernel<<<(N_DIM * (size_t)K_DIM / 8) / 256, 256>>>(w);

    static bool attr_set = false;
    if (!attr_set) {
        cudaFuncSetAttribute(ternary_gemm_kernel,
                             cudaFuncAttributeMaxDynamicSharedMemorySize, SMEM_TOTAL);
        attr_set = true;
    }
    const int grid = (M_DIM / BM) * (N_DIM / BN);     // 2048
    ternary_gemm_kernel<<<grid, THREADS, SMEM_TOTAL>>>(x, out);
}

// round 11
// speedup vs baseline: 1.5331x; 1.5331x over previous
#include <cuda_runtime.h>
#include <cuda_fp16.h>
#include <cstdint>
#include <cstddef>

// ============================================================================
// out[8192,4096] = x[8192,4096] @ ternarize(W)[4096,4096]^T, fp32.
// FP16 mma.sync.m16n8k16 path: 2x K per MMA vs tf32 m16n8k8 (tensor pipe was
// the measured binder at ~62% with 16cyc/MMA). Ternary W exact in fp16;
// x->fp16 rn has same half-ulp bound (2^-11) as tf32 rna; fp32 accumulate.
//  - W pre-pass: ternarize -> fp16 (32 MB static, proven-safe size).
//  - A: fp32 via cp.async, converted in-register (1 LDS.64 + 1 cvt per frag).
//  - No XOR swizzle: padded pitches (A 160B, B 80B) are provably conflict-free.
// ============================================================================
#define M_DIM 8192
#define N_DIM 4096
#define K_DIM 4096

#define BM 128
#define BN 128
#define BK 32                       // k elements per stage
#define STAGES 3
#define K_ITERS (K_DIM / BK)        // 128
#define THREADS 256

#define A_PITCH 160                 // 128B fp32 data + 32B pad
#define B_PITCH 80                  // 64B fp16 data + 16B pad
#define A_STAGE_BYTES (BM * A_PITCH)            // 20480
#define B_STAGE_BYTES (BN * B_PITCH)            // 10240
#define STAGE_BYTES   (A_STAGE_BYTES + B_STAGE_BYTES)   // 30720
#define SMEM_TOTAL    (STAGES * STAGE_BYTES)            // 92160

// Ternarized fp16 weights (exact). 32 MB static — same scale as proven R2/R10.
__device__ __align__(16) __half g_Wh[(size_t)N_DIM * K_DIM];

// ============================================================================
// Helpers
// ============================================================================
__device__ __forceinline__ uint32_t smem_u32(const void* p) {
    uint32_t a;
    asm("{ .reg .u64 t; cvta.to.shared.u64 t, %1; cvt.u32.u64 %0, t; }" : "=r"(a) : "l"(p));
    return a;
}
__device__ __forceinline__ void cp_async16(uint32_t dst, const void* src) {
    asm volatile("cp.async.cg.shared.global [%0], [%1], 16;" :: "r"(dst), "l"(src) : "memory");
}
__device__ __forceinline__ void cp_commit() { asm volatile("cp.async.commit_group;" ::: "memory"); }
__device__ __forceinline__ void cp_wait1()  { asm volatile("cp.async.wait_group 1;" ::: "memory"); }

__device__ __forceinline__ float2 lds_f32x2(uint32_t addr) {
    float2 v;
    asm volatile("ld.shared.v2.f32 {%0, %1}, [%2];" : "=f"(v.x), "=f"(v.y) : "r"(addr));
    return v;
}
__device__ __forceinline__ uint32_t lds_u32(uint32_t addr) {
    uint32_t v;
    asm volatile("ld.shared.b32 %0, [%1];" : "=r"(v) : "r"(addr));
    return v;
}
// pack two f32 -> f16x2 reg: lo half = f_even, hi half = f_odd
__device__ __forceinline__ uint32_t cvt_f16x2(float f_even, float f_odd) {
    uint32_t d;
    asm("cvt.rn.f16x2.f32 %0, %2, %1;" : "=r"(d) : "f"(f_even), "f"(f_odd));
    return d;
}
__device__ __forceinline__ void mma_f16(float& d0, float& d1, float& d2, float& d3,
                                        uint32_t a0, uint32_t a1, uint32_t a2, uint32_t a3,
                                        uint32_t b0, uint32_t b1) {
    asm volatile("mma.sync.aligned.m16n8k16.row.col.f32.f16.f16.f32 "
                 "{%0,%1,%2,%3}, {%4,%5,%6,%7}, {%8,%9}, {%0,%1,%2,%3};"
                 : "+f"(d0), "+f"(d1), "+f"(d2), "+f"(d3)
                 : "r"(a0), "r"(a1), "r"(a2), "r"(a3), "r"(b0), "r"(b1));
}

// ============================================================================
// W ternarize -> fp16: sign(rint(w)) in {-1,0,1}, exact in fp16.
// Each thread: 8 weights -> 8 halves (16B store).
// ============================================================================
__device__ __forceinline__ float tern(float w) {
    float r = rintf(w);                       // half-to-even, matches jnp.round
    return (r > 0.f) ? 1.f : ((r < 0.f) ? -1.f : 0.f);
}
__global__ void cvt_w_kernel(const float* __restrict__ w) {
    size_t o = (size_t)blockIdx.x * blockDim.x + threadIdx.x;   // octet id, 2097152
    const float4* p = reinterpret_cast<const float4*>(w + o * 8);
    float4 v0 = p[0];
    float4 v1 = p[1];
    uint32_t h0 = cvt_f16x2(tern(v0.x), tern(v0.y));
    uint32_t h1 = cvt_f16x2(tern(v0.z), tern(v0.w));
    uint32_t h2 = cvt_f16x2(tern(v1.x), tern(v1.y));
    uint32_t h3 = cvt_f16x2(tern(v1.z), tern(v1.w));
    *reinterpret_cast<uint4*>(reinterpret_cast<__half*>(g_Wh) + o * 8) =
        make_uint4(h0, h1, h2, h3);
}

// ============================================================================
// GEMM kernel
// ============================================================================
__global__ __launch_bounds__(THREADS, 2) void ternary_gemm_f16(
    const float* __restrict__ x, float* __restrict__ out) {
    extern __shared__ char smem[];
    const uint32_t sb = smem_u32(smem);
    const int tid = threadIdx.x;

    // supergrouped rasterization: 8 M-tiles x 32 N-tiles per supergroup
    const int TILES_N = N_DIM / BN;           // 32
    const int GM = 8;
    const int per_super = GM * TILES_N;       // 256
    const int sg = blockIdx.x / per_super;
    const int r  = blockIdx.x % per_super;
    const int M0 = (sg * GM + (r % GM)) * BM;
    const int N0 = (r / GM) * BN;

    // --- loaders ---
    // A: 1024 16B-chunks/stage (128 rows x 8 chunks of fp32), 4 per thread
    // B:  512 16B-chunks/stage (128 rows x 4 chunks of fp16), 2 per thread
    const float* srcA[4];
    uint32_t dstA[4];
#pragma unroll
    for (int t = 0; t < 4; t++) {
        int cid = tid + t * 256;
        int row = cid >> 3;
        int ch  = cid & 7;
        srcA[t] = x + (size_t)(M0 + row) * K_DIM + ch * 4;
        dstA[t] = (uint32_t)(row * A_PITCH + ch * 16);
    }
    const __half* srcB[2];
    uint32_t dstB[2];
#pragma unroll
    for (int t = 0; t < 2; t++) {
        int cid = tid + t * 256;
        int row = cid >> 2;
        int ch  = cid & 3;
        srcB[t] = g_Wh + (size_t)(N0 + row) * K_DIM + ch * 8;
        dstB[t] = (uint32_t)(row * B_PITCH + ch * 16);
    }

    auto issue_stage = [&](int i) {
        const uint32_t aS = sb + (i % STAGES) * STAGE_BYTES;
        const uint32_t bS = aS + A_STAGE_BYTES;
        const int kf = i * BK;                 // fp32 element offset for A
#pragma unroll
        for (int t = 0; t < 4; t++) cp_async16(aS + dstA[t], srcA[t] + kf);
#pragma unroll
        for (int t = 0; t < 2; t++) cp_async16(bS + dstB[t], srcB[t] + kf);
        cp_commit();
    };

    issue_stage(0);
    issue_stage(1);

    // --- warp tiling: 4 warps on M (32 rows), 2 on N (64 cols) ---
    const int wid = tid >> 5;
    const int lane = tid & 31;
    const int grp = lane >> 2;                // 0..7
    const int qid = lane & 3;                 // 0..3
    const int wmBase = (wid & 3) * 32;
    const int wnBase = (wid >> 2) * 64;
    const uint32_t aRow = (uint32_t)((wmBase + grp) * A_PITCH + qid * 8);
    const uint32_t bRow = (uint32_t)((wnBase + grp) * B_PITCH + qid * 4);

    float acc[2][8][4];
#pragma unroll
    for (int mt = 0; mt < 2; mt++)
#pragma unroll
        for (int nt = 0; nt < 8; nt++)
#pragma unroll
            for (int j = 0; j < 4; j++) acc[mt][nt][j] = 0.f;

#pragma unroll 1
    for (int i = 0; i < K_ITERS; i++) {
        cp_wait1();
        __syncthreads();
        if (i + 2 < K_ITERS) issue_stage(i + 2);
        else cp_commit();                      // uniform group accounting

        const uint32_t aS = sb + (i % STAGES) * STAGE_BYTES;
        const uint32_t bS = aS + A_STAGE_BYTES;

#pragma unroll
        for (int ks = 0; ks < 2; ks++) {
            // A fragments: m16n8k16 -> 4 regs per m-tile; each reg = one
            // LDS.64 (cols 2qid,2qid+1 as fp32) + one cvt to f16x2.
            // byte-in-row: ks*64 + qid*8 (+32 for the k+8 half; +8 rows for a1/a3)
            uint32_t a[2][4];
#pragma unroll
            for (int mt = 0; mt < 2; mt++) {
                const uint32_t base = aS + aRow + (uint32_t)(mt * 16 * A_PITCH + ks * 64);
                float2 f0 = lds_f32x2(base);
                float2 f1 = lds_f32x2(base + 8 * A_PITCH);
                float2 f2 = lds_f32x2(base + 32);
                float2 f3 = lds_f32x2(base + 8 * A_PITCH + 32);
                a[mt][0] = cvt_f16x2(f0.x, f0.y);
                a[mt][1] = cvt_f16x2(f1.x, f1.y);
                a[mt][2] = cvt_f16x2(f2.x, f2.y);
                a[mt][3] = cvt_f16x2(f3.x, f3.y);
            }
            // B fragments: 2 regs per n-tile, direct f16x2 LDS.32
            // byte-in-row: ks*32 + qid*4 (+16 for k+8)
#pragma unroll
            for (int nt = 0; nt < 8; nt++) {
                const uint32_t nb = bS + bRow + (uint32_t)(nt * 8 * B_PITCH + ks * 32);
                const uint32_t b0 = lds_u32(nb);
                const uint32_t b1 = lds_u32(nb + 16);
#pragma unroll
                for (int mt = 0; mt < 2; mt++)
                    mma_f16(acc[mt][nt][0], acc[mt][nt][1], acc[mt][nt][2], acc[mt][nt][3],
                            a[mt][0], a[mt][1], a[mt][2], a[mt][3], b0, b1);
            }
        }
    }

    // --- epilogue: STG.64 (float2), coalesced per 8-col n-tile ---
#pragma unroll
    for (int mt = 0; mt < 2; mt++) {
        int row0 = M0 + wmBase + mt * 16 + grp;
#pragma unroll
        for (int nt = 0; nt < 8; nt++) {
            int col = N0 + wnBase + nt * 8 + qid * 2;
            float2 v0 = make_float2(acc[mt][nt][0], acc[mt][nt][1]);
            float2 v1 = make_float2(acc[mt][nt][2], acc[mt][nt][3]);
            *reinterpret_cast<float2*>(out + (size_t)row0 * N_DIM + col)       = v0;
            *reinterpret_cast<float2*>(out + (size_t)(row0 + 8) * N_DIM + col) = v1;
        }
    }
}

// ============================================================================
// Launch
// ============================================================================
extern "C" void kernel_launch(void* const* d_in, const int* in_sizes, int n_in,
                              void* d_out, int out_size) {
    const float* x = (const float*)d_in[0];       // [8192, 4096]
    const float* w = (const float*)d_in[1];       // [4096, 4096]
    float* out = (float*)d_out;                   // [8192, 4096]

    cvt_w_kernel<<<(N_DIM * (size_t)K_DIM / 8) / 256, 256>>>(w);

    static bool attr_set = false;
    if (!attr_set) {
        cudaFuncSetAttribute(ternary_gemm_f16,
                             cudaFuncAttributeMaxDynamicSharedMemorySize, SMEM_TOTAL);
        attr_set = true;
    }
    const int grid = (M_DIM / BM) * (N_DIM / BN);     // 2048
    ternary_gemm_f16<<<grid, THREADS, SMEM_TOTAL>>>(x, out);
}